// round 8
// baseline (speedup 1.0000x reference)
#include <cuda_runtime.h>
#include <cuda_bf16.h>
#include <cstdint>

// ---------------------------------------------------------------------------
// MultiDimensionalRNN: skewed 2D RNN (diagonal recurrence) + FC head.
//
//   act[r,c] = tanh(k0*act[r-1,c-1] + k1*act[r,c-1] + bs + in[r,c])
//   in[r,c]  = w*img[r, c-r] + b   if r <= c <= r+W-1,  else b
//   unskewed[r,c] = act[r, r+c];  out = unskewed.reshape(4096,1024) @ fc_w^T + fc_b
//
// 32 single-warp pipeline stages (64 rows each, 2 adjacent rows per lane).
// State kept in r-form: r = 1/(1 + 2^(LAM2*x)), tanh(x) = 1 - 2r.
// Cross-stage handoff: global boundary ring + chunked acquire/release flags.
// Boundary reads use ld.relaxed.gpu (L2) to dodge stale-L1 lines.
// ---------------------------------------------------------------------------

#define HH 2048
#define WW 2048
#define NSTAGE 32
#define RPL 2
#define ROWS_PER_STAGE (32 * RPL)   // 64
#define CH 16                        // columns per sync chunk
#define NCOL 4096                    // 4095 needed; col 4095 harmless (out of band)
#define NCHUNK (NCOL / CH)           // 256
#define FC_IN 1024
#define FC_OUT 10
#define M_ROWS ((HH * WW) / FC_IN)   // 4096

__device__ float g_U[(size_t)HH * WW];      // unskewed activations (16 MB)
__device__ float g_Bnd[NSTAGE * NCOL];      // boundary-row r-values per column
__device__ int   g_flag[NSTAGE];            // chunks completed per stage

// ---------------- PTX helpers ----------------
__device__ __forceinline__ float ex2f(float x) {
    float r; asm("ex2.approx.ftz.f32 %0, %1;" : "=f"(r) : "f"(x)); return r;
}
__device__ __forceinline__ float rcpf(float x) {
    float r; asm("rcp.approx.ftz.f32 %0, %1;" : "=f"(r) : "f"(x)); return r;
}
__device__ __forceinline__ int ld_acq(const int* p) {
    int v;
    asm volatile("ld.acquire.gpu.global.s32 %0, [%1];" : "=r"(v) : "l"(p) : "memory");
    return v;
}
__device__ __forceinline__ void st_rel(int* p, int v) {
    asm volatile("st.release.gpu.global.s32 [%0], %1;" :: "l"(p), "r"(v) : "memory");
}
// Strong (gpu-scope) load: reads at L2, never a stale L1 line.
__device__ __forceinline__ float ld_l2(const float* p) {
    float v;
    asm volatile("ld.relaxed.gpu.global.f32 %0, [%1];" : "=f"(v) : "l"(p) : "memory");
    return v;
}

// ---------------- flag reset (runs before scan on every replay) ------------
__global__ void reset_kernel() {
    if (threadIdx.x < NSTAGE) g_flag[threadIdx.x] = 0;
}

// ---------------- wavefront scan ----------------
__global__ void __launch_bounds__(32, 1)
scan_kernel(const float* __restrict__ img,
            const float* __restrict__ w_in,    const float* __restrict__ b_in,
            const float* __restrict__ w_state, const float* __restrict__ b_state)
{
    const int s    = blockIdx.x;
    const int lane = threadIdx.x;

    const float LAM2 = 2.8853900817779268f;   // 2*log2(e)
    const float k0 = w_state[0];
    const float k1 = w_state[1];
    const float A  = -2.0f * LAM2 * k0;       // coeff on r_up
    const float B  = -2.0f * LAM2 * k1;       // coeff on r_self
    const float Cc = LAM2 * (k0 + k1 + b_state[0] + b_in[0]);
    const float Wl = LAM2 * w_in[0];

    const int R0 = s * ROWS_PER_STAGE + lane * 2;   // upper row of this lane
    const int R1 = R0 + 1;                          // lower row
    // img value for row R at column c: img[R*2048 + (c-R)] = (img + R*2047)[c]
    const float* q0 = img + (size_t)R0 * (WW - 1);
    const float* q1 = img + (size_t)R1 * (WW - 1);
    // unskewed store: g_U[R*2048 + (c-R)] = (g_U + R*2047)[c]
    float* u0 = g_U + (size_t)R0 * (WW - 1);
    float* u1 = g_U + (size_t)R1 * (WW - 1);
    const int lo0 = R0, hi0 = R0 + WW - 1;
    const int lo1 = R1, hi1 = R1 + WW - 1;

    float*       bout = g_Bnd + s * NCOL;
    const float* bin  = g_Bnd + (s - 1) * NCOL;

    float r0 = 0.5f, r1 = 0.5f;               // r-form of h = 0

    for (int k = 0; k < NCHUNK; k++) {
        const int c0 = k * CH;

        // --- acquire producer chunk, then fetch boundary values (L2-strong) ---
        float bnd[CH];
        if (s > 0) {
            if (lane == 0) {
                while (ld_acq(&g_flag[s - 1]) <= k) { }
            }
            __syncwarp();
            #pragma unroll
            for (int j = 0; j < CH; j++) {
                int idx = c0 + j - 1;
                bnd[j] = (idx >= 0) ? ld_l2(bin + idx) : 0.5f;
            }
        } else {
            #pragma unroll
            for (int j = 0; j < CH; j++) bnd[j] = 0.5f;
        }

        // --- per-cell input constants (affine of image, or pad constant) ---
        float g0[CH], g1[CH];
        #pragma unroll
        for (int j = 0; j < CH; j++) {
            int c = c0 + j;
            g0[j] = (c >= lo0 && c <= hi0) ? fmaf(Wl, __ldg(q0 + c), Cc) : Cc;
            g1[j] = (c >= lo1 && c <= hi1) ? fmaf(Wl, __ldg(q1 + c), Cc) : Cc;
        }

        // --- the recurrence ---
        #pragma unroll
        for (int j = 0; j < CH; j++) {
            int c = c0 + j;
            float up   = __shfl_up_sync(0xffffffffu, r1, 1);  // lane-1's row R0-1, prev col
            float r0up = (lane == 0) ? bnd[j] : up;
            float a0 = fmaf(A, r0up, fmaf(B, r0, g0[j]));
            float a1 = fmaf(A, r0,   fmaf(B, r1, g1[j]));     // R1's up-neighbor = old r0
            float n0 = rcpf(1.0f + ex2f(a0));
            float n1 = rcpf(1.0f + ex2f(a1));
            if (c >= lo0 && c <= hi0) u0[c] = fmaf(-2.0f, n0, 1.0f);
            if (c >= lo1 && c <= hi1) u1[c] = fmaf(-2.0f, n1, 1.0f);
            if (lane == 31) bout[c] = n1;                     // boundary row (r-form)
            r0 = n0; r1 = n1;
        }

        if (lane == 31) st_rel(&g_flag[s], k + 1);
    }
}

// ---------------- FC head: warp-per-row GEMV ----------------
__global__ void __launch_bounds__(256)
fc_kernel(const float* __restrict__ fc_w, const float* __restrict__ fc_b,
          float* __restrict__ out)
{
    __shared__ float sw[FC_OUT][FC_IN];   // 40 KB
    const int tid = threadIdx.x;
    for (int i = tid; i < FC_OUT * FC_IN; i += blockDim.x)
        (&sw[0][0])[i] = fc_w[i];
    __syncthreads();

    const int warp = tid >> 5, lane = tid & 31;
    const int m = blockIdx.x * (blockDim.x >> 5) + warp;
    const float* x = g_U + (size_t)m * FC_IN;

    float acc[FC_OUT];
    #pragma unroll
    for (int o = 0; o < FC_OUT; o++) acc[o] = 0.0f;

    #pragma unroll 4
    for (int k = lane; k < FC_IN; k += 32) {
        float xv = x[k];
        #pragma unroll
        for (int o = 0; o < FC_OUT; o++)
            acc[o] = fmaf(xv, sw[o][k], acc[o]);
    }
    #pragma unroll
    for (int o = 0; o < FC_OUT; o++) {
        #pragma unroll
        for (int d = 16; d > 0; d >>= 1)
            acc[o] += __shfl_down_sync(0xffffffffu, acc[o], d);
    }
    if (lane == 0) {
        #pragma unroll
        for (int o = 0; o < FC_OUT; o++)
            out[(size_t)m * FC_OUT + o] = acc[o] + fc_b[o];
    }
}

// ---------------- launch ----------------
extern "C" void kernel_launch(void* const* d_in, const int* in_sizes, int n_in,
                              void* d_out, int out_size)
{
    (void)in_sizes; (void)n_in; (void)out_size;
    const float* x       = (const float*)d_in[0];  // [1,2048,2048]
    const float* w_in    = (const float*)d_in[1];  // [1]
    const float* b_in    = (const float*)d_in[2];  // [1]
    const float* w_state = (const float*)d_in[3];  // [2] = {k0, k1}
    const float* b_state = (const float*)d_in[4];  // [1]
    const float* fc_w    = (const float*)d_in[5];  // [10,1024]
    const float* fc_b    = (const float*)d_in[6];  // [10]
    float* out = (float*)d_out;                    // [4096,10]

    reset_kernel<<<1, 32>>>();
    scan_kernel<<<NSTAGE, 32>>>(x, w_in, b_in, w_state, b_state);
    fc_kernel<<<M_ROWS / 8, 256>>>(fc_w, fc_b, out);
}

// round 9
// speedup vs baseline: 1.5005x; 1.5005x over previous
#include <cuda_runtime.h>
#include <cuda_bf16.h>
#include <cstdint>

// ---------------------------------------------------------------------------
// MultiDimensionalRNN: skewed 2D RNN (diagonal recurrence) + FC head.
//
//   act[r,c] = tanh(k0*act[r-1,c-1] + k1*act[r,c-1] + bs + in[r,c])     (skewed)
//
// R9: divergence-free memory. Prep kernel materializes the pre-affined input
// in a SKEWED, PADDED layout g_In[r][c] (stride 4096, so chunk segments are
// float4-aligned for every row). Scan keeps a 16-column chunk of inputs and
// outputs in registers (float4 LDG/STG), cutting L1tex wavefronts ~4x vs R8's
// per-column scattered accesses. Activations stored skewed in g_A; FC reads
// them contiguously at per-row offset.
//
// 32 single-warp pipeline stages (64 rows each, 2 adjacent rows per lane).
// State in r-form: r = 1/(1 + 2^(LAM2*x)), tanh(x) = 1 - 2r.
// Cross-stage handoff: boundary ring + chunked acquire/release flags;
// boundary data read with ld.relaxed.gpu (L2-strong, no stale L1).
// ---------------------------------------------------------------------------

#define HH 2048
#define WW 2048
#define WS 4096                     // padded skewed stride (floats)
#define NSTAGE 32
#define ROWS_PER_STAGE 64           // 32 lanes * 2 rows
#define CH 16                       // columns per sync chunk (4 float4 / row)
#define NCOL 4096                   // 4095 needed; col 4095 harmless
#define NCHUNK (NCOL / CH)          // 256
#define FC_IN 1024
#define FC_OUT 10
#define M_ROWS ((HH * WW) / FC_IN)  // 4096

__device__ float g_In[(size_t)HH * WS];     // pre-affined skewed input (32 MB)
__device__ float g_A [(size_t)HH * WS];     // skewed activations h (32 MB)
__device__ float g_Bnd[NSTAGE * NCOL];      // boundary-row r-values per column
__device__ int   g_flag[NSTAGE];            // chunks completed per stage

// ---------------- PTX helpers ----------------
__device__ __forceinline__ float ex2f(float x) {
    float r; asm("ex2.approx.ftz.f32 %0, %1;" : "=f"(r) : "f"(x)); return r;
}
__device__ __forceinline__ float rcpf(float x) {
    float r; asm("rcp.approx.ftz.f32 %0, %1;" : "=f"(r) : "f"(x)); return r;
}
__device__ __forceinline__ int ld_acq(const int* p) {
    int v;
    asm volatile("ld.acquire.gpu.global.s32 %0, [%1];" : "=r"(v) : "l"(p) : "memory");
    return v;
}
__device__ __forceinline__ void st_rel(int* p, int v) {
    asm volatile("st.release.gpu.global.s32 [%0], %1;" :: "l"(p), "r"(v) : "memory");
}
__device__ __forceinline__ float ld_l2(const float* p) {
    float v;
    asm volatile("ld.relaxed.gpu.global.f32 %0, [%1];" : "=f"(v) : "l"(p) : "memory");
    return v;
}

// ---------------- prep: skew + affine + flag reset ----------------
// g_In[r][c] = Wl*img[r][c-r] + Cc  if 0 <= c-r < W,  else Cc
__global__ void __launch_bounds__(256)
prep_kernel(const float* __restrict__ img,
            const float* __restrict__ w_in,    const float* __restrict__ b_in,
            const float* __restrict__ w_state, const float* __restrict__ b_state)
{
    const float LAM2 = 2.8853900817779268f;     // 2*log2(e)
    const float Wl = LAM2 * w_in[0];
    const float Cc = LAM2 * (w_state[0] + w_state[1] + b_state[0] + b_in[0]);

    int t = blockIdx.x * blockDim.x + threadIdx.x;   // [0, 2048*1024)
    int r  = t >> 10;                                // row
    int c0 = (t & 1023) << 2;                        // col base (float4)
    float v[4];
    #pragma unroll
    for (int u = 0; u < 4; u++) {
        int d = c0 + u - r;                          // unskewed column
        v[u] = (d >= 0 && d < WW)
             ? fmaf(Wl, __ldg(img + (size_t)r * WW + d), Cc)
             : Cc;
    }
    *(float4*)(g_In + (size_t)r * WS + c0) = make_float4(v[0], v[1], v[2], v[3]);

    if (t < NSTAGE) g_flag[t] = 0;                   // fold flag reset in here
}

// ---------------- wavefront scan ----------------
__global__ void __launch_bounds__(32, 1)
scan_kernel(const float* __restrict__ w_state, const float* __restrict__ b_state)
{
    const int s    = blockIdx.x;
    const int lane = threadIdx.x;

    const float LAM2 = 2.8853900817779268f;
    const float A = -2.0f * LAM2 * w_state[0];       // coeff on r_up
    const float B = -2.0f * LAM2 * w_state[1];       // coeff on r_self
    (void)b_state;                                   // folded into g_In by prep

    const int R0 = s * ROWS_PER_STAGE + lane * 2;
    const int R1 = R0 + 1;
    const float4* p0 = (const float4*)(g_In + (size_t)R0 * WS);
    const float4* p1 = (const float4*)(g_In + (size_t)R1 * WS);
    float4* o0p = (float4*)(g_A + (size_t)R0 * WS);
    float4* o1p = (float4*)(g_A + (size_t)R1 * WS);

    float*       bout = g_Bnd + s * NCOL;
    const float* bin  = g_Bnd + (s - 1) * NCOL;

    float r0 = 0.5f, r1 = 0.5f;                      // r-form of h = 0

    // prefetch chunk 0 inputs
    float4 in0[4], in1[4];
    #pragma unroll
    for (int t = 0; t < 4; t++) { in0[t] = p0[t]; in1[t] = p1[t]; }

    for (int k = 0; k < NCHUNK; k++) {
        const int c0 = k * CH;
        const int q0 = c0 >> 2;                      // float4 index of chunk base

        // --- software-pipeline: issue next-chunk loads BEFORE the spin ---
        float4 nx0[4], nx1[4];
        if (k + 1 < NCHUNK) {
            #pragma unroll
            for (int t = 0; t < 4; t++) { nx0[t] = p0[q0 + 4 + t]; nx1[t] = p1[q0 + 4 + t]; }
        }

        // --- acquire producer chunk, then fetch boundary values (L2) ---
        float bnd[CH];
        if (s > 0) {
            if (lane == 0) {
                while (ld_acq(&g_flag[s - 1]) <= k) { }
            }
            __syncwarp();
            #pragma unroll
            for (int j = 0; j < CH; j++) {
                int idx = c0 + j - 1;
                bnd[j] = (idx >= 0) ? ld_l2(bin + idx) : 0.5f;
            }
        } else {
            #pragma unroll
            for (int j = 0; j < CH; j++) bnd[j] = 0.5f;
        }

        // unpack input float4s to scalars (register renaming)
        float g0[CH], g1[CH];
        #pragma unroll
        for (int t = 0; t < 4; t++) {
            g0[4*t+0] = in0[t].x; g0[4*t+1] = in0[t].y; g0[4*t+2] = in0[t].z; g0[4*t+3] = in0[t].w;
            g1[4*t+0] = in1[t].x; g1[4*t+1] = in1[t].y; g1[4*t+2] = in1[t].z; g1[4*t+3] = in1[t].w;
        }

        // --- the recurrence (outputs accumulate in registers) ---
        float o0[CH], o1[CH];
        #pragma unroll
        for (int j = 0; j < CH; j++) {
            float up   = __shfl_up_sync(0xffffffffu, r1, 1); // lane-1 row R0-1, prev col
            float r0up = (lane == 0) ? bnd[j] : up;
            float a0 = fmaf(A, r0up, fmaf(B, r0, g0[j]));
            float a1 = fmaf(A, r0,   fmaf(B, r1, g1[j]));    // R1's up = old r0
            float n0 = rcpf(1.0f + ex2f(a0));
            float n1 = rcpf(1.0f + ex2f(a1));
            o0[j] = fmaf(-2.0f, n0, 1.0f);
            o1[j] = fmaf(-2.0f, n1, 1.0f);
            if (lane == 31) bout[c0 + j] = n1;               // boundary (r-form)
            r0 = n0; r1 = n1;
        }

        // --- aligned float4 stores of the whole chunk ---
        #pragma unroll
        for (int t = 0; t < 4; t++) {
            o0p[q0 + t] = make_float4(o0[4*t], o0[4*t+1], o0[4*t+2], o0[4*t+3]);
            o1p[q0 + t] = make_float4(o1[4*t], o1[4*t+1], o1[4*t+2], o1[4*t+3]);
        }

        if (lane == 31) st_rel(&g_flag[s], k + 1);

        #pragma unroll
        for (int t = 0; t < 4; t++) { in0[t] = nx0[t]; in1[t] = nx1[t]; }
    }
}

// ---------------- FC head: warp-per-row GEMV over skewed g_A ----------------
__global__ void __launch_bounds__(256)
fc_kernel(const float* __restrict__ fc_w, const float* __restrict__ fc_b,
          float* __restrict__ out)
{
    __shared__ float sw[FC_OUT][FC_IN];   // 40 KB
    const int tid = threadIdx.x;
    for (int i = tid; i < FC_OUT * FC_IN; i += blockDim.x)
        (&sw[0][0])[i] = fc_w[i];
    __syncthreads();

    const int warp = tid >> 5, lane = tid & 31;
    const int m = blockIdx.x * (blockDim.x >> 5) + warp;
    const int r = m >> 1, h = m & 1;
    // unskewed[r, c] = act[r, r+c];  FC row m covers cols h*1024 .. h*1024+1023
    const float* x = g_A + (size_t)r * WS + r + h * FC_IN;

    float acc[FC_OUT];
    #pragma unroll
    for (int o = 0; o < FC_OUT; o++) acc[o] = 0.0f;

    #pragma unroll 4
    for (int k = lane; k < FC_IN; k += 32) {
        float xv = x[k];
        #pragma unroll
        for (int o = 0; o < FC_OUT; o++)
            acc[o] = fmaf(xv, sw[o][k], acc[o]);
    }
    #pragma unroll
    for (int o = 0; o < FC_OUT; o++) {
        #pragma unroll
        for (int d = 16; d > 0; d >>= 1)
            acc[o] += __shfl_down_sync(0xffffffffu, acc[o], d);
    }
    if (lane == 0) {
        #pragma unroll
        for (int o = 0; o < FC_OUT; o++)
            out[(size_t)m * FC_OUT + o] = acc[o] + fc_b[o];
    }
}

// ---------------- launch ----------------
extern "C" void kernel_launch(void* const* d_in, const int* in_sizes, int n_in,
                              void* d_out, int out_size)
{
    (void)in_sizes; (void)n_in; (void)out_size;
    const float* x       = (const float*)d_in[0];  // [1,2048,2048]
    const float* w_in    = (const float*)d_in[1];  // [1]
    const float* b_in    = (const float*)d_in[2];  // [1]
    const float* w_state = (const float*)d_in[3];  // [2] = {k0, k1}
    const float* b_state = (const float*)d_in[4];  // [1]
    const float* fc_w    = (const float*)d_in[5];  // [10,1024]
    const float* fc_b    = (const float*)d_in[6];  // [10]
    float* out = (float*)d_out;                    // [4096,10]

    prep_kernel<<<(HH * (WS / 4)) / 256, 256>>>(x, w_in, b_in, w_state, b_state);
    scan_kernel<<<NSTAGE, 32>>>(w_state, b_state);
    fc_kernel<<<M_ROWS / 8, 256>>>(fc_w, fc_b, out);
}